// round 16
// baseline (speedup 1.0000x reference)
#include <cuda_runtime.h>
#include <cuda_bf16.h>
#include <cstdint>

#define LSEQ 252
#define HID 768
#define MLP 770
#define NLAB 36
#define BATCH 2
#define KP 784            // MLP padded to 49*16
#define KP2 392           // KP/2 (bf16x2 pairs)
#define NPH1 1540         // 2*MLP
#define MROWS 504         // BATCH*LSEQ
#define LL (LSEQ*LSEQ)    // 63504
#define LL4 (LL/4)        // 15876
#define W1STRIDE 1537     // 2*HID+1
#define NPART 16          // softmax partial-sum slots per (b,k)
#define NCHUNK 49         // k16 chunks
#define JT 64             // j's per block
#define AJW 392           // words (bf16x2 pairs) per row; 392 mod 32 = 8

// ---- scratch (device globals; no dynamic allocation allowed) ----
__device__ float g_W1r[NPH1 * HID];            // repacked W1 (B operand rows)
__device__ float g_Ai[MROWS * KP];             // Ai fp32, zero-padded cols [770,784)
__device__ uint32_t g_Ajh[MROWS * KP2];        // Aj bf16x2, PAIR-PERMUTED, pads zeroed
__device__ float g_Cc[3 * KP];                 // b1 + c*w1c, c=0..2
__device__ uint32_t g_W2b[40 * KP2];           // W2 40x784 bf16, k16-element-permuted
__device__ unsigned g_maxbits[BATCH * NLAB];   // per-(b,k) max (>=0, float bits)
__device__ float g_psum[BATCH * NLAB * NPART]; // partial exp-sums
__device__ int g_dummy_sink;                   // k_dummy target

// ---------------------------------------------------------------------------
// pair permutation within each 8-pair (16-element) group:
// stored order [p0,p4,p1,p5,p2,p6,p3,p7] -> LDS.64 at 2*kq gives (p_kq, p_{kq+4})
__device__ __forceinline__ int permp(int p) {
    int g = p >> 3, q = p & 7;
    return g * 8 + ((q & 3) << 1) + (q >> 2);
}

__device__ __forceinline__ unsigned pack_bf16(float lo, float hi) {
    unsigned r;
    asm("cvt.rn.bf16x2.f32 %0, %1, %2;" : "=r"(r) : "f"(hi), "f"(lo));
    return r;
}
__device__ __forceinline__ __nv_bfloat162 u2b(uint32_t x) {
    return *(__nv_bfloat162*)&x;
}
__device__ __forceinline__ uint32_t b2u(__nv_bfloat162 x) {
    return *(uint32_t*)&x;
}

// tf32 mma m16n8k8 (phase-1 GEMM)
__device__ __forceinline__ void mma_tf32(float* d, float a0, float a1, float a2, float a3,
                                         float b0, float b1) {
    asm volatile(
        "mma.sync.aligned.m16n8k8.row.col.f32.tf32.tf32.f32 "
        "{%0,%1,%2,%3},{%4,%5,%6,%7},{%8,%9},{%0,%1,%2,%3};\n"
        : "+f"(d[0]), "+f"(d[1]), "+f"(d[2]), "+f"(d[3])
        : "r"(__float_as_uint(a0)), "r"(__float_as_uint(a1)),
          "r"(__float_as_uint(a2)), "r"(__float_as_uint(a3)),
          "r"(__float_as_uint(b0)), "r"(__float_as_uint(b1)));
}
// bf16 mma m16n8k16 (main GEMM)
__device__ __forceinline__ void mma_bf16(float* d, unsigned a0, unsigned a1, unsigned a2,
                                         unsigned a3, unsigned b0, unsigned b1) {
    asm volatile(
        "mma.sync.aligned.m16n8k16.row.col.f32.bf16.bf16.f32 "
        "{%0,%1,%2,%3},{%4,%5,%6,%7},{%8,%9},{%0,%1,%2,%3};\n"
        : "+f"(d[0]), "+f"(d[1]), "+f"(d[2]), "+f"(d[3])
        : "r"(a0), "r"(a1), "r"(a2), "r"(a3), "r"(b0), "r"(b1));
}

// ---------------------------------------------------------------------------
// Prep: repack W1, C vectors, W2 (k16 element perm), pads, reset max.
__global__ void k_prep(const float* __restrict__ W1, const float* __restrict__ b1,
                       const float* __restrict__ W2) {
    int idx = blockIdx.x * blockDim.x + threadIdx.x;
    int stride = gridDim.x * blockDim.x;
    for (int t = idx; t < NPH1 * HID; t += stride) {
        int n = t / HID, k = t - n * HID;
        g_W1r[t] = (n < MLP) ? W1[n * W1STRIDE + k] : W1[(n - MLP) * W1STRIDE + HID + k];
    }
    for (int t = idx; t < 3 * KP; t += stride) {
        int c = t / KP, h = t - c * KP;
        g_Cc[t] = (h < MLP) ? (b1[h] + (float)c * W1[h * W1STRIDE + 2 * HID]) : 0.0f;
    }
    for (int t = idx; t < 40 * KP2; t += stride) {  // build as bf16x2 words
        int n = t / KP2, p = t - n * KP2;
        int ch = p >> 3, pin = p & 7;
        int pos0 = pin * 2, pos1 = pin * 2 + 1;
        int q0 = pos0 >> 2, q1 = pos1 >> 2;
        int k0 = ch * 16 + (((pos0 & 3) < 2) ? (2 * q0 + (pos0 & 1)) : (8 + 2 * q0 + (pos0 & 1)));
        int k1 = ch * 16 + (((pos1 & 3) < 2) ? (2 * q1 + (pos1 & 1)) : (8 + 2 * q1 + (pos1 & 1)));
        float v0 = (n < NLAB && k0 < MLP) ? W2[n * MLP + k0] : 0.0f;
        float v1 = (n < NLAB && k1 < MLP) ? W2[n * MLP + k1] : 0.0f;
        g_W2b[t] = pack_bf16(v0, v1);
    }
    for (int t = idx; t < MROWS * (KP - MLP); t += stride) {
        int m = t / (KP - MLP), c = MLP + (t - m * (KP - MLP));
        g_Ai[m * KP + c] = 0.0f;
    }
    for (int t = idx; t < MROWS * 7; t += stride) {  // Aj pad pairs 385..391 (perm-closed)
        int m = t / 7, p = 385 + (t - m * 7);
        g_Ajh[m * KP2 + p] = 0u;
    }
    for (int t = idx; t < BATCH * NLAB; t += stride) g_maxbits[t] = 0u;
}

// ---------------------------------------------------------------------------
// Phase 1: [504x768] @ [768x1540] tf32 GEMM -> g_Ai (fp32) / g_Ajh (bf16x2, permuted).
__global__ __launch_bounds__(128) void k_ph1(const float* __restrict__ hidden) {
    __shared__ float As[64 * 36];
    __shared__ float Bs[64 * 36];
    const int tid = threadIdx.x, lane = tid & 31, w = tid >> 5;
    const int m0 = blockIdx.y * 64, n0 = blockIdx.x * 64;
    const int wm = w >> 1, wn = w & 1;
    const int r = lane >> 2, kq = lane & 3;

    float acc[2][4][4];
#pragma unroll
    for (int a = 0; a < 2; a++)
#pragma unroll
        for (int b = 0; b < 4; b++)
#pragma unroll
            for (int c = 0; c < 4; c++) acc[a][b][c] = 0.0f;

    for (int kc = 0; kc < 24; kc++) {
        const int k0 = kc * 32;
#pragma unroll
        for (int p = 0; p < 4; p++) {
            int i = tid + p * 128;
            int row = i >> 3, c8 = i & 7;
            int m = m0 + row;
            float4 v = make_float4(0.f, 0.f, 0.f, 0.f);
            if (m < MROWS) {
                int b = m / LSEQ, l = m - b * LSEQ;
                v = *(const float4*)&hidden[((size_t)(b * (LSEQ + 1) + l + 1)) * HID + k0 + c8 * 4];
            }
            *(float4*)&As[row * 36 + c8 * 4] = v;
        }
#pragma unroll
        for (int p = 0; p < 4; p++) {
            int i = tid + p * 128;
            int row = i >> 3, c8 = i & 7;
            int n = n0 + row;
            float4 v = make_float4(0.f, 0.f, 0.f, 0.f);
            if (n < NPH1) v = *(const float4*)&g_W1r[(size_t)n * HID + k0 + c8 * 4];
            *(float4*)&Bs[row * 36 + c8 * 4] = v;
        }
        __syncthreads();
#pragma unroll
        for (int kk = 0; kk < 4; kk++) {
            const int kb = kk * 8 + kq;
            float a[2][4];
#pragma unroll
            for (int mf = 0; mf < 2; mf++) {
                int rb = wm * 32 + mf * 16 + r;
                a[mf][0] = As[rb * 36 + kb];
                a[mf][1] = As[(rb + 8) * 36 + kb];
                a[mf][2] = As[rb * 36 + kb + 4];
                a[mf][3] = As[(rb + 8) * 36 + kb + 4];
            }
#pragma unroll
            for (int nf = 0; nf < 4; nf++) {
                int nr = wn * 32 + nf * 8 + r;
                float b0 = Bs[nr * 36 + kb];
                float b1 = Bs[nr * 36 + kb + 4];
                mma_tf32(acc[0][nf], a[0][0], a[0][1], a[0][2], a[0][3], b0, b1);
                mma_tf32(acc[1][nf], a[1][0], a[1][1], a[1][2], a[1][3], b0, b1);
            }
        }
        __syncthreads();
    }
#pragma unroll
    for (int mf = 0; mf < 2; mf++) {
#pragma unroll
        for (int nf = 0; nf < 4; nf++) {
            int mg = m0 + wm * 32 + mf * 16 + r;
            int ng = n0 + wn * 32 + nf * 8 + kq * 2;
            if (ng < NPH1) {
                if (ng < MLP) {
                    if (mg < MROWS)
                        *(float2*)&g_Ai[(size_t)mg * KP + ng] =
                            make_float2(acc[mf][nf][0], acc[mf][nf][1]);
                    if (mg + 8 < MROWS)
                        *(float2*)&g_Ai[(size_t)(mg + 8) * KP + ng] =
                            make_float2(acc[mf][nf][2], acc[mf][nf][3]);
                } else {
                    int p = permp((ng - MLP) >> 1);
                    if (mg < MROWS)
                        g_Ajh[(size_t)mg * KP2 + p] = pack_bf16(acc[mf][nf][0], acc[mf][nf][1]);
                    if (mg + 8 < MROWS)
                        g_Ajh[(size_t)(mg + 8) * KP2 + p] =
                            pack_bf16(acc[mf][nf][2], acc[mf][nf][3]);
                }
            }
        }
    }
}

// ---------------------------------------------------------------------------
// Dummy: occupies launch slot 3 so ncu (which captures the 4th launch) lands
// on k_main. Deterministic, trivial.
__global__ void k_dummy() {
    if (threadIdx.x == 0) g_dummy_sink = 1;
}

// ---------------------------------------------------------------------------
// Main fused kernel: 8i x 64j slab, 512 threads (16 warps = 4 il-pairs x 4 jh).
// Each warp owns TWO m-tiles (il, il+4) sharing the same 16 j-rows: aj and B
// fragments loaded once per 10 MMAs (-39% smem traffic vs 1 m-tile/warp).
// Grid 4x16x2 = 128 CTAs, exactly 2 slabs each (perfect balance).
#define SMW_AJ 0                      // [64][392] uint32
#define SMW_AIC (JT * AJW)            // [24][392]
#define SMW_W2 (SMW_AIC + 24 * AJW)   // [40][392]
#define SMW_B2 (SMW_W2 + 40 * AJW)    // 40 floats
#define SMW_CF (SMW_B2 + 40)          // 512 bytes (128 words)
#define SMEM_MAIN ((SMW_CF + 128) * 4)

__global__ __launch_bounds__(512, 1) void k_main(const int* __restrict__ spans,
                                                 const int* __restrict__ smask,
                                                 const float* __restrict__ b2,
                                                 float* __restrict__ out) {
    extern __shared__ uint32_t smw[];
    uint32_t* AjS = smw + SMW_AJ;
    uint32_t* AiC = smw + SMW_AIC;
    uint32_t* W2s = smw + SMW_W2;
    float* b2s = (float*)(smw + SMW_B2);
    unsigned char* cf = (unsigned char*)(smw + SMW_CF);

    const int tid = threadIdx.x;
    const int b = blockIdx.z, itc = blockIdx.y, jt = blockIdx.x;
    const int j0 = jt * JT;
    const int s = spans[b * 2], e = spans[b * 2 + 1];

    // ---- one-time prologue ----
    for (int u = tid; u < JT * AJW; u += 512) {
        int row = u / AJW, p = u - row * AJW;
        int j = j0 + row;
        AjS[u] = (j < LSEQ) ? g_Ajh[(size_t)(b * LSEQ + j) * KP2 + p] : 0u;
    }
    for (int u = tid; u < 40 * AJW / 4; u += 512)
        ((uint4*)W2s)[u] = ((const uint4*)g_W2b)[u];
    if (tid < 40) b2s[tid] = (tid < NLAB) ? b2[tid] : 0.0f;

    const int lane = tid & 31, w = tid >> 5;
    const int ilp = w >> 2, jh = w & 3;
    const int il_a = ilp, il_b = ilp + 4;
    const int r = lane >> 2, kq = lane & 3;
    const int jr0 = jh * 16 + r, jr1 = jr0 + 8;
    const int jg0 = j0 + jr0, jg1 = j0 + jr1;
    const __nv_bfloat162 z2 = __float2bfloat162_rn(0.0f);

    __syncthreads();

    float bb[5][2];
#pragma unroll
    for (int t = 0; t < 5; t++) {
        int k0 = t * 8 + kq * 2;
        bb[t][0] = (k0 < NLAB) ? b2s[k0] : 0.0f;
        bb[t][1] = (k0 + 1 < NLAB) ? b2s[k0 + 1] : 0.0f;
    }
    float mx[5][2];
#pragma unroll
    for (int t = 0; t < 5; t++) mx[t][0] = mx[t][1] = 0.0f;

    for (int sl = 0; sl < 2; sl++) {
        const int i0 = (itc * 2 + sl) * 8;   // slab of 8 i's; tail rows guarded

        // build AiC (bf16x2, pair-permuted), 24 rows; zero for i >= LSEQ
        for (int u = tid; u < 24 * AJW; u += 512) {
            int rc = u / AJW, p = u - rc * AJW;
            int ill = rc / 3, c = rc - ill * 3;
            uint32_t val = 0u;
            if (i0 + ill < LSEQ) {
                float2 a = *(const float2*)&g_Ai[(size_t)(b * LSEQ + i0 + ill) * KP + 2 * p];
                float2 cc = *(const float2*)&g_Cc[c * KP + 2 * p];
                val = pack_bf16(a.x + cc.x, a.y + cc.y);
            }
            AiC[rc * AJW + permp(p)] = val;
        }
        // flags: 8 x 64
        {
            int ill = tid >> 6, jl = tid & 63;
            int i = i0 + ill, j = j0 + jl;
            int c = 0, valid = 0;
            if (i < LSEQ && j < LSEQ) {
                valid = (smask[i * LSEQ + j] >= 1) ? 1 : 0;
                if (s <= i && i <= j && j <= e) c = (i == s && j == e) ? 2 : 1;
            }
            cf[tid] = (unsigned char)(c | (valid << 2));
        }
        __syncthreads();

        const int f0a = cf[il_a * JT + jr0], f1a = cf[il_a * JT + jr1];
        const int f0b = cf[il_b * JT + jr0], f1b = cf[il_b * JT + jr1];
        const uint32_t* aj0p = AjS + jr0 * AJW + 2 * kq;
        const uint32_t* aj1p = AjS + jr1 * AJW + 2 * kq;
        const uint32_t* ac0a = AiC + (il_a * 3 + (f0a & 3)) * AJW + 2 * kq;
        const uint32_t* ac1a = AiC + (il_a * 3 + (f1a & 3)) * AJW + 2 * kq;
        const uint32_t* ac0b = AiC + (il_b * 3 + (f0b & 3)) * AJW + 2 * kq;
        const uint32_t* ac1b = AiC + (il_b * 3 + (f1b & 3)) * AJW + 2 * kq;
        const uint32_t* wpp = W2s + r * AJW + 2 * kq;

        float acc[2][5][4];
#pragma unroll
        for (int g = 0; g < 2; g++)
#pragma unroll
            for (int t = 0; t < 5; t++)
#pragma unroll
                for (int q = 0; q < 4; q++) acc[g][t][q] = 0.0f;

#pragma unroll 2
        for (int ks = 0; ks < NCHUNK; ks++) {
            const int off = ks * 8;
            uint2 vj0 = *(const uint2*)(aj0p + off);
            uint2 vj1 = *(const uint2*)(aj1p + off);
            uint2 v0a = *(const uint2*)(ac0a + off);
            uint2 v1a = *(const uint2*)(ac1a + off);
            uint2 v0b = *(const uint2*)(ac0b + off);
            uint2 v1b = *(const uint2*)(ac1b + off);
            unsigned a0a = b2u(__hmax2(__hadd2(u2b(vj0.x), u2b(v0a.x)), z2));
            unsigned a2a = b2u(__hmax2(__hadd2(u2b(vj0.y), u2b(v0a.y)), z2));
            unsigned a1a = b2u(__hmax2(__hadd2(u2b(vj1.x), u2b(v1a.x)), z2));
            unsigned a3a = b2u(__hmax2(__hadd2(u2b(vj1.y), u2b(v1a.y)), z2));
            unsigned a0b = b2u(__hmax2(__hadd2(u2b(vj0.x), u2b(v0b.x)), z2));
            unsigned a2b = b2u(__hmax2(__hadd2(u2b(vj0.y), u2b(v0b.y)), z2));
            unsigned a1b = b2u(__hmax2(__hadd2(u2b(vj1.x), u2b(v1b.x)), z2));
            unsigned a3b = b2u(__hmax2(__hadd2(u2b(vj1.y), u2b(v1b.y)), z2));
#pragma unroll
            for (int t = 0; t < 5; t++) {
                uint2 bv = *(const uint2*)(wpp + t * 8 * AJW + off);
                mma_bf16(acc[0][t], a0a, a1a, a2a, a3a, bv.x, bv.y);
                mma_bf16(acc[1][t], a0b, a1b, a2b, a3b, bv.x, bv.y);
            }
        }

        // epilogue: +b2, mask, store; track per-k max (both il's)
#pragma unroll
        for (int g = 0; g < 2; g++) {
            const int i = i0 + ilp + 4 * g;
            if (i < LSEQ) {
                const int ff0 = g ? f0b : f0a, ff1 = g ? f1b : f1a;
                const int v0 = (ff0 >> 2) & 1, v1 = (ff1 >> 2) & 1;
#pragma unroll
                for (int t = 0; t < 5; t++) {
                    int k0 = t * 8 + kq * 2;
                    if (k0 < NLAB) {
                        if (jg0 < LSEQ) {
                            float s0 = v0 ? (acc[g][t][0] + bb[t][0]) : 0.0f;
                            float s1 = v0 ? (acc[g][t][1] + bb[t][1]) : 0.0f;
                            size_t p0 = (size_t)(b * NLAB + k0) * LL + (size_t)i * LSEQ + jg0;
                            out[p0] = s0;
                            out[p0 + LL] = s1;
                            mx[t][0] = fmaxf(mx[t][0], s0);
                            mx[t][1] = fmaxf(mx[t][1], s1);
                        }
                        if (jg1 < LSEQ) {
                            float s0 = v1 ? (acc[g][t][2] + bb[t][0]) : 0.0f;
                            float s1 = v1 ? (acc[g][t][3] + bb[t][1]) : 0.0f;
                            size_t p1 = (size_t)(b * NLAB + k0) * LL + (size_t)i * LSEQ + jg1;
                            out[p1] = s0;
                            out[p1 + LL] = s1;
                            mx[t][0] = fmaxf(mx[t][0], s0);
                            mx[t][1] = fmaxf(mx[t][1], s1);
                        }
                    }
                }
            }
        }
        __syncthreads();  // epilogue done before next-slab AiC/cf overwrite
    }

    // fold max over r-lanes (lane = r*4+kq), then atomicMax per label
#pragma unroll
    for (int t = 0; t < 5; t++) {
#pragma unroll
        for (int q = 0; q < 2; q++) {
            float m = mx[t][q];
            m = fmaxf(m, __shfl_xor_sync(0xFFFFFFFFu, m, 4));
            m = fmaxf(m, __shfl_xor_sync(0xFFFFFFFFu, m, 8));
            m = fmaxf(m, __shfl_xor_sync(0xFFFFFFFFu, m, 16));
            int k0 = t * 8 + kq * 2 + q;
            if (r == 0 && k0 < NLAB)
                atomicMax(&g_maxbits[b * NLAB + k0], __float_as_uint(m));
        }
    }
}

// ---------------------------------------------------------------------------
// Partial sum of exp(x - M); 4 independent accumulator chains + 2-way load ILP.
__global__ __launch_bounds__(256) void k_sumexp(const float* __restrict__ out) {
    const int bk = blockIdx.y;
    const float4* p = (const float4*)(out + (size_t)bk * LL);
    const float M = __uint_as_float(g_maxbits[bk]);
    const float L2E = 1.4426950408889634f;
    const float nML2E = -M * L2E;
    const int STR = NPART * 256;
    float s0 = 0.f, s1 = 0.f, s2 = 0.f, s3 = 0.f;
    for (int t = blockIdx.x * 256 + threadIdx.x; t < LL4; t += 2 * STR) {
        float4 v = p[t];
        float4 u = make_float4(0.f, 0.f, 0.f, 0.f);
        int t2 = t + STR;
        bool hi = (t2 < LL4);
        if (hi) u = p[t2];
        s0 += exp2f(fmaf(v.x, L2E, nML2E));
        s1 += exp2f(fmaf(v.y, L2E, nML2E));
        s2 += exp2f(fmaf(v.z, L2E, nML2E));
        s3 += exp2f(fmaf(v.w, L2E, nML2E));
        if (hi) {
            s0 += exp2f(fmaf(u.x, L2E, nML2E));
            s1 += exp2f(fmaf(u.y, L2E, nML2E));
            s2 += exp2f(fmaf(u.z, L2E, nML2E));
            s3 += exp2f(fmaf(u.w, L2E, nML2E));
        }
    }
    float s = (s0 + s1) + (s2 + s3);
#pragma unroll
    for (int o = 16; o > 0; o >>= 1) s += __shfl_xor_sync(0xFFFFFFFFu, s, o);
    __shared__ float sm[8];
    if ((threadIdx.x & 31) == 0) sm[threadIdx.x >> 5] = s;
    __syncthreads();
    if (threadIdx.x == 0) {
        float ss = 0.f;
#pragma unroll
        for (int q = 0; q < 8; q++) ss += sm[q];
        g_psum[bk * NPART + blockIdx.x] = ss;  // fixed slot -> deterministic
    }
}

// Combine partials (fixed order) + subtract lse.
__global__ __launch_bounds__(256) void k_sub(float* __restrict__ out) {
    const int bk = blockIdx.y;
    __shared__ float lse_s;
    if (threadIdx.x == 0) {
        float M = __uint_as_float(g_maxbits[bk]);
        float s = 0.f;
#pragma unroll
        for (int q = 0; q < NPART; q++) s += g_psum[bk * NPART + q];
        lse_s = M + logf(s);
    }
    __syncthreads();
    const float lse = lse_s;
    int t = blockIdx.x * 256 + threadIdx.x;
    if (t < LL4) {
        float4* p = (float4*)(out + (size_t)bk * LL);
        float4 v = p[t];
        v.x -= lse;
        v.y -= lse;
        v.z -= lse;
        v.w -= lse;
        p[t] = v;
    }
}

// ---------------------------------------------------------------------------
extern "C" void kernel_launch(void* const* d_in, const int* in_sizes, int n_in,
                              void* d_out, int out_size) {
    const float* hidden = (const float*)d_in[0];
    const int* spans = (const int*)d_in[1];
    const int* smask = (const int*)d_in[2];
    const float* W1 = (const float*)d_in[3];
    const float* b1 = (const float*)d_in[4];
    const float* W2 = (const float*)d_in[5];
    const float* b2 = (const float*)d_in[6];
    float* out = (float*)d_out;

    cudaFuncSetAttribute(k_main, cudaFuncAttributeMaxDynamicSharedMemorySize, SMEM_MAIN);

    k_prep<<<256, 256>>>(W1, b1, W2);
    k_ph1<<<dim3(25, 8), 128>>>(hidden);
    k_dummy<<<1, 32>>>();   // launch slot 3 -> ncu's 4th-launch capture = k_main
    k_main<<<dim3(4, 16, 2), 512, SMEM_MAIN>>>(spans, smask, b2, out);
    k_sumexp<<<dim3(NPART, BATCH * NLAB), 256>>>(out);
    k_sub<<<dim3((LL4 + 255) / 256, BATCH * NLAB), 256>>>(out);
}

// round 17
// speedup vs baseline: 1.0224x; 1.0224x over previous
#include <cuda_runtime.h>
#include <cuda_bf16.h>
#include <cstdint>

#define LSEQ 252
#define HID 768
#define MLP 770
#define NLAB 36
#define BATCH 2
#define KP 784            // MLP padded to 49*16
#define KP2 392           // KP/2 (bf16x2 pairs)
#define NPH1 1540         // 2*MLP
#define MROWS 504         // BATCH*LSEQ
#define LL (LSEQ*LSEQ)    // 63504
#define LL4 (LL/4)        // 15876
#define W1STRIDE 1537     // 2*HID+1
#define NPART 16          // softmax partial-sum slots per (b,k)
#define NCHUNK 49         // k16 chunks
#define JT 64             // j's per block
#define ISLAB 7           // i's per slab (252 = 36*7; 2 slabs/CTA, grid y=18)
#define AJW 392           // words (bf16x2 pairs) per row; 392 mod 32 = 8

// ---- scratch (device globals; no dynamic allocation allowed) ----
__device__ float g_W1r[NPH1 * HID];            // repacked W1 (B operand rows)
__device__ float g_Ai[MROWS * KP];             // Ai fp32, zero-padded cols [770,784)
__device__ uint32_t g_Ajh[MROWS * KP2];        // Aj bf16x2, PAIR-PERMUTED, pads zeroed
__device__ float g_Cc[3 * KP];                 // b1 + c*w1c, c=0..2
__device__ uint32_t g_W2b[40 * KP2];           // W2 40x784 bf16, k16-element-permuted
__device__ unsigned g_maxbits[BATCH * NLAB];   // per-(b,k) max (>=0, float bits)
__device__ float g_psum[BATCH * NLAB * NPART]; // partial exp-sums

// ---------------------------------------------------------------------------
// pair permutation within each 8-pair (16-element) group:
// stored order [p0,p4,p1,p5,p2,p6,p3,p7] -> LDS.64 at 2*kq gives (p_kq, p_{kq+4})
__device__ __forceinline__ int permp(int p) {
    int g = p >> 3, q = p & 7;
    return g * 8 + ((q & 3) << 1) + (q >> 2);
}

__device__ __forceinline__ unsigned pack_bf16(float lo, float hi) {
    unsigned r;
    asm("cvt.rn.bf16x2.f32 %0, %1, %2;" : "=r"(r) : "f"(hi), "f"(lo));
    return r;
}
__device__ __forceinline__ __nv_bfloat162 u2b(uint32_t x) {
    return *(__nv_bfloat162*)&x;
}
__device__ __forceinline__ uint32_t b2u(__nv_bfloat162 x) {
    return *(uint32_t*)&x;
}

// tf32 mma m16n8k8 (phase-1 GEMM)
__device__ __forceinline__ void mma_tf32(float* d, float a0, float a1, float a2, float a3,
                                         float b0, float b1) {
    asm volatile(
        "mma.sync.aligned.m16n8k8.row.col.f32.tf32.tf32.f32 "
        "{%0,%1,%2,%3},{%4,%5,%6,%7},{%8,%9},{%0,%1,%2,%3};\n"
        : "+f"(d[0]), "+f"(d[1]), "+f"(d[2]), "+f"(d[3])
        : "r"(__float_as_uint(a0)), "r"(__float_as_uint(a1)),
          "r"(__float_as_uint(a2)), "r"(__float_as_uint(a3)),
          "r"(__float_as_uint(b0)), "r"(__float_as_uint(b1)));
}
// bf16 mma m16n8k16 (main GEMM)
__device__ __forceinline__ void mma_bf16(float* d, unsigned a0, unsigned a1, unsigned a2,
                                         unsigned a3, unsigned b0, unsigned b1) {
    asm volatile(
        "mma.sync.aligned.m16n8k16.row.col.f32.bf16.bf16.f32 "
        "{%0,%1,%2,%3},{%4,%5,%6,%7},{%8,%9},{%0,%1,%2,%3};\n"
        : "+f"(d[0]), "+f"(d[1]), "+f"(d[2]), "+f"(d[3])
        : "r"(a0), "r"(a1), "r"(a2), "r"(a3), "r"(b0), "r"(b1));
}

// ---------------------------------------------------------------------------
// Prep: repack W1, C vectors, W2 (k16 element perm), pads, reset max.
__global__ void k_prep(const float* __restrict__ W1, const float* __restrict__ b1,
                       const float* __restrict__ W2) {
    int idx = blockIdx.x * blockDim.x + threadIdx.x;
    int stride = gridDim.x * blockDim.x;
    for (int t = idx; t < NPH1 * HID; t += stride) {
        int n = t / HID, k = t - n * HID;
        g_W1r[t] = (n < MLP) ? W1[n * W1STRIDE + k] : W1[(n - MLP) * W1STRIDE + HID + k];
    }
    for (int t = idx; t < 3 * KP; t += stride) {
        int c = t / KP, h = t - c * KP;
        g_Cc[t] = (h < MLP) ? (b1[h] + (float)c * W1[h * W1STRIDE + 2 * HID]) : 0.0f;
    }
    for (int t = idx; t < 40 * KP2; t += stride) {  // build as bf16x2 words
        int n = t / KP2, p = t - n * KP2;
        int ch = p >> 3, pin = p & 7;
        int pos0 = pin * 2, pos1 = pin * 2 + 1;
        int q0 = pos0 >> 2, q1 = pos1 >> 2;
        int k0 = ch * 16 + (((pos0 & 3) < 2) ? (2 * q0 + (pos0 & 1)) : (8 + 2 * q0 + (pos0 & 1)));
        int k1 = ch * 16 + (((pos1 & 3) < 2) ? (2 * q1 + (pos1 & 1)) : (8 + 2 * q1 + (pos1 & 1)));
        float v0 = (n < NLAB && k0 < MLP) ? W2[n * MLP + k0] : 0.0f;
        float v1 = (n < NLAB && k1 < MLP) ? W2[n * MLP + k1] : 0.0f;
        g_W2b[t] = pack_bf16(v0, v1);
    }
    for (int t = idx; t < MROWS * (KP - MLP); t += stride) {
        int m = t / (KP - MLP), c = MLP + (t - m * (KP - MLP));
        g_Ai[m * KP + c] = 0.0f;
    }
    for (int t = idx; t < MROWS * 7; t += stride) {  // Aj pad pairs 385..391 (perm-closed)
        int m = t / 7, p = 385 + (t - m * 7);
        g_Ajh[m * KP2 + p] = 0u;
    }
    for (int t = idx; t < BATCH * NLAB; t += stride) g_maxbits[t] = 0u;
}

// ---------------------------------------------------------------------------
// Phase 1: [504x768] @ [768x1540] tf32 GEMM -> g_Ai (fp32) / g_Ajh (bf16x2, permuted).
__global__ __launch_bounds__(128) void k_ph1(const float* __restrict__ hidden) {
    __shared__ float As[64 * 36];
    __shared__ float Bs[64 * 36];
    const int tid = threadIdx.x, lane = tid & 31, w = tid >> 5;
    const int m0 = blockIdx.y * 64, n0 = blockIdx.x * 64;
    const int wm = w >> 1, wn = w & 1;
    const int r = lane >> 2, kq = lane & 3;

    float acc[2][4][4];
#pragma unroll
    for (int a = 0; a < 2; a++)
#pragma unroll
        for (int b = 0; b < 4; b++)
#pragma unroll
            for (int c = 0; c < 4; c++) acc[a][b][c] = 0.0f;

    for (int kc = 0; kc < 24; kc++) {
        const int k0 = kc * 32;
#pragma unroll
        for (int p = 0; p < 4; p++) {
            int i = tid + p * 128;
            int row = i >> 3, c8 = i & 7;
            int m = m0 + row;
            float4 v = make_float4(0.f, 0.f, 0.f, 0.f);
            if (m < MROWS) {
                int b = m / LSEQ, l = m - b * LSEQ;
                v = *(const float4*)&hidden[((size_t)(b * (LSEQ + 1) + l + 1)) * HID + k0 + c8 * 4];
            }
            *(float4*)&As[row * 36 + c8 * 4] = v;
        }
#pragma unroll
        for (int p = 0; p < 4; p++) {
            int i = tid + p * 128;
            int row = i >> 3, c8 = i & 7;
            int n = n0 + row;
            float4 v = make_float4(0.f, 0.f, 0.f, 0.f);
            if (n < NPH1) v = *(const float4*)&g_W1r[(size_t)n * HID + k0 + c8 * 4];
            *(float4*)&Bs[row * 36 + c8 * 4] = v;
        }
        __syncthreads();
#pragma unroll
        for (int kk = 0; kk < 4; kk++) {
            const int kb = kk * 8 + kq;
            float a[2][4];
#pragma unroll
            for (int mf = 0; mf < 2; mf++) {
                int rb = wm * 32 + mf * 16 + r;
                a[mf][0] = As[rb * 36 + kb];
                a[mf][1] = As[(rb + 8) * 36 + kb];
                a[mf][2] = As[rb * 36 + kb + 4];
                a[mf][3] = As[(rb + 8) * 36 + kb + 4];
            }
#pragma unroll
            for (int nf = 0; nf < 4; nf++) {
                int nr = wn * 32 + nf * 8 + r;
                float b0 = Bs[nr * 36 + kb];
                float b1 = Bs[nr * 36 + kb + 4];
                mma_tf32(acc[0][nf], a[0][0], a[0][1], a[0][2], a[0][3], b0, b1);
                mma_tf32(acc[1][nf], a[1][0], a[1][1], a[1][2], a[1][3], b0, b1);
            }
        }
        __syncthreads();
    }
#pragma unroll
    for (int mf = 0; mf < 2; mf++) {
#pragma unroll
        for (int nf = 0; nf < 4; nf++) {
            int mg = m0 + wm * 32 + mf * 16 + r;
            int ng = n0 + wn * 32 + nf * 8 + kq * 2;
            if (ng < NPH1) {
                if (ng < MLP) {
                    if (mg < MROWS)
                        *(float2*)&g_Ai[(size_t)mg * KP + ng] =
                            make_float2(acc[mf][nf][0], acc[mf][nf][1]);
                    if (mg + 8 < MROWS)
                        *(float2*)&g_Ai[(size_t)(mg + 8) * KP + ng] =
                            make_float2(acc[mf][nf][2], acc[mf][nf][3]);
                } else {
                    int p = permp((ng - MLP) >> 1);
                    if (mg < MROWS)
                        g_Ajh[(size_t)mg * KP2 + p] = pack_bf16(acc[mf][nf][0], acc[mf][nf][1]);
                    if (mg + 8 < MROWS)
                        g_Ajh[(size_t)(mg + 8) * KP2 + p] =
                            pack_bf16(acc[mf][nf][2], acc[mf][nf][3]);
                }
            }
        }
    }
}

// ---------------------------------------------------------------------------
// Zero the output tensor (masked positions are never written by k_main).
// Also occupies launch slot 3 so ncu's 4th-launch capture = k_main.
__global__ __launch_bounds__(512) void k_zero(float4* __restrict__ out) {
    int t = blockIdx.x * 512 + threadIdx.x;
    if (t < BATCH * NLAB * LL4) out[t] = make_float4(0.f, 0.f, 0.f, 0.f);
}

// ---------------------------------------------------------------------------
// Main fused kernel with VALID-ROW COMPACTION. Slab = 7 i's x 64 j's (448
// positions, E[valid]=224 -> ~14 m-tiles vs 28 dense). Valid (ill,jl,c)
// compacted into idx[]; each warp runs one 16-row m-tile over all 5 n-tiles,
// gathering A fragments by index and scatter-storing results.
#define SMW_AJ 0                      // [64][392] uint32
#define SMW_AIC (JT * AJW)            // [21][392]
#define SMW_W2 (SMW_AIC + 21 * AJW)   // [40][392]
#define SMW_B2 (SMW_W2 + 40 * AJW)    // 40 floats
#define SMW_IDX (SMW_B2 + 40)         // 480 entries
#define SMW_WC (SMW_IDX + 480)        // wcnt[16] + nv
#define SMEM_MAIN ((SMW_WC + 20) * 4)

__global__ __launch_bounds__(512, 1) void k_main(const int* __restrict__ spans,
                                                 const int* __restrict__ smask,
                                                 const float* __restrict__ b2,
                                                 float* __restrict__ out) {
    extern __shared__ uint32_t smw[];
    uint32_t* AjS = smw + SMW_AJ;
    uint32_t* AiC = smw + SMW_AIC;
    uint32_t* W2s = smw + SMW_W2;
    float* b2s = (float*)(smw + SMW_B2);
    uint32_t* idxA = smw + SMW_IDX;
    int* wcnt = (int*)(smw + SMW_WC);
    int* s_nv = (int*)(smw + SMW_WC + 16);

    const int tid = threadIdx.x;
    const int b = blockIdx.z, itc = blockIdx.y, jt = blockIdx.x;
    const int j0 = jt * JT;
    const int s = spans[b * 2], e = spans[b * 2 + 1];

    // ---- one-time prologue ----
    for (int u = tid; u < JT * AJW; u += 512) {
        int row = u / AJW, p = u - row * AJW;
        int j = j0 + row;
        AjS[u] = (j < LSEQ) ? g_Ajh[(size_t)(b * LSEQ + j) * KP2 + p] : 0u;
    }
    for (int u = tid; u < 40 * AJW / 4; u += 512)
        ((uint4*)W2s)[u] = ((const uint4*)g_W2b)[u];
    if (tid < 40) b2s[tid] = (tid < NLAB) ? b2[tid] : 0.0f;

    const int lane = tid & 31, w = tid >> 5;
    const int r = lane >> 2, kq = lane & 3;
    const __nv_bfloat162 z2 = __float2bfloat162_rn(0.0f);

    __syncthreads();

    float bb[5][2];
#pragma unroll
    for (int t = 0; t < 5; t++) {
        int k0 = t * 8 + kq * 2;
        bb[t][0] = (k0 < NLAB) ? b2s[k0] : 0.0f;
        bb[t][1] = (k0 + 1 < NLAB) ? b2s[k0 + 1] : 0.0f;
    }
    float mx[5][2];
#pragma unroll
    for (int t = 0; t < 5; t++) mx[t][0] = mx[t][1] = 0.0f;

    for (int sl = 0; sl < 2; sl++) {
        const int i0 = (itc * 2 + sl) * ISLAB;  // i0+6 <= 251, never OOB

        // build AiC (bf16x2, pair-permuted), 21 rows
        for (int u = tid; u < 21 * AJW; u += 512) {
            int rc = u / AJW, p = u - rc * AJW;
            int ill = rc / 3, c = rc - ill * 3;
            float2 a = *(const float2*)&g_Ai[(size_t)(b * LSEQ + i0 + ill) * KP + 2 * p];
            float2 cc = *(const float2*)&g_Cc[c * KP + 2 * p];
            AiC[rc * AJW + permp(p)] = pack_bf16(a.x + cc.x, a.y + cc.y);
        }

        // flags + ballot compaction (tid-ordered -> deterministic)
        int valid = 0, enc = 0;
        {
            int ill = tid >> 6, jl = tid & 63;
            int i = i0 + ill, j = j0 + jl;
            if (tid < ISLAB * JT && j < LSEQ) {
                valid = (smask[i * LSEQ + j] >= 1) ? 1 : 0;
                int c = 0;
                if (s <= i && i <= j && j <= e) c = (i == s && j == e) ? 2 : 1;
                enc = (ill << 8) | (jl << 2) | c;
            }
        }
        unsigned bal = __ballot_sync(0xFFFFFFFFu, valid);
        if (lane == 0) wcnt[w] = __popc(bal);
        __syncthreads();
        int base = 0;
#pragma unroll
        for (int q = 0; q < 16; q++) base += (q < w) ? wcnt[q] : 0;
        if (valid)
            idxA[base + __popc(bal & ((1u << lane) - 1u))] = (uint32_t)enc;
        if (tid == 0) {
            int nv = 0;
#pragma unroll
            for (int q = 0; q < 16; q++) nv += wcnt[q];
            *s_nv = nv;
        }
        __syncthreads();
        const int nv = *s_nv;
        if (tid < 16) idxA[nv + tid] = 0u;  // pad rows (ill=0,jl=0,c=0), not stored
        __syncthreads();
        const int ntiles = (nv + 15) >> 4;

        for (int t16 = w; t16 < ntiles; t16 += 16) {
            const uint32_t e0 = idxA[t16 * 16 + r];
            const uint32_t e1 = idxA[t16 * 16 + 8 + r];
            const int jl0 = (e0 >> 2) & 63, il0 = e0 >> 8, c0 = e0 & 3;
            const int jl1 = (e1 >> 2) & 63, il1 = e1 >> 8, c1 = e1 & 3;
            const uint32_t* aj0p = AjS + jl0 * AJW + 2 * kq;
            const uint32_t* aj1p = AjS + jl1 * AJW + 2 * kq;
            const uint32_t* ac0p = AiC + (il0 * 3 + c0) * AJW + 2 * kq;
            const uint32_t* ac1p = AiC + (il1 * 3 + c1) * AJW + 2 * kq;
            const uint32_t* wpp = W2s + r * AJW + 2 * kq;

            float acc[5][4];
#pragma unroll
            for (int t = 0; t < 5; t++)
#pragma unroll
                for (int q = 0; q < 4; q++) acc[t][q] = 0.0f;

#pragma unroll 2
            for (int ks = 0; ks < NCHUNK; ks++) {
                const int off = ks * 8;
                uint2 vj0 = *(const uint2*)(aj0p + off);
                uint2 vc0 = *(const uint2*)(ac0p + off);
                uint2 vj1 = *(const uint2*)(aj1p + off);
                uint2 vc1 = *(const uint2*)(ac1p + off);
                unsigned a0 = b2u(__hmax2(__hadd2(u2b(vj0.x), u2b(vc0.x)), z2));
                unsigned a2 = b2u(__hmax2(__hadd2(u2b(vj0.y), u2b(vc0.y)), z2));
                unsigned a1 = b2u(__hmax2(__hadd2(u2b(vj1.x), u2b(vc1.x)), z2));
                unsigned a3 = b2u(__hmax2(__hadd2(u2b(vj1.y), u2b(vc1.y)), z2));
#pragma unroll
                for (int t = 0; t < 5; t++) {
                    uint2 bv = *(const uint2*)(wpp + t * 8 * AJW + off);
                    mma_bf16(acc[t], a0, a1, a2, a3, bv.x, bv.y);
                }
            }

            // scatter epilogue: +b2, store, track max
            const int row0 = t16 * 16 + r, row1 = row0 + 8;
            const int go0 = (row0 < nv), go1 = (row1 < nv);
            const size_t p0base =
                (size_t)b * NLAB * LL + (size_t)(i0 + il0) * LSEQ + (j0 + jl0);
            const size_t p1base =
                (size_t)b * NLAB * LL + (size_t)(i0 + il1) * LSEQ + (j0 + jl1);
#pragma unroll
            for (int t = 0; t < 5; t++) {
                int k0 = t * 8 + kq * 2;
                if (k0 < NLAB) {
                    if (go0) {
                        float s0 = acc[t][0] + bb[t][0];
                        float s1 = acc[t][1] + bb[t][1];
                        out[p0base + (size_t)k0 * LL] = s0;
                        out[p0base + (size_t)(k0 + 1) * LL] = s1;
                        mx[t][0] = fmaxf(mx[t][0], s0);
                        mx[t][1] = fmaxf(mx[t][1], s1);
                    }
                    if (go1) {
                        float s0 = acc[t][2] + bb[t][0];
                        float s1 = acc[t][3] + bb[t][1];
                        out[p1base + (size_t)k0 * LL] = s0;
                        out[p1base + (size_t)(k0 + 1) * LL] = s1;
                        mx[t][0] = fmaxf(mx[t][0], s0);
                        mx[t][1] = fmaxf(mx[t][1], s1);
                    }
                }
            }
        }
        __syncthreads();  // all warps done before next slab overwrites AiC/idx
    }

    // fold max over r-lanes (lane = r*4+kq), then atomicMax per label
#pragma unroll
    for (int t = 0; t < 5; t++) {
#pragma unroll
        for (int q = 0; q < 2; q++) {
            float m = mx[t][q];
            m = fmaxf(m, __shfl_xor_sync(0xFFFFFFFFu, m, 4));
            m = fmaxf(m, __shfl_xor_sync(0xFFFFFFFFu, m, 8));
            m = fmaxf(m, __shfl_xor_sync(0xFFFFFFFFu, m, 16));
            int k0 = t * 8 + kq * 2 + q;
            if (r == 0 && k0 < NLAB)
                atomicMax(&g_maxbits[b * NLAB + k0], __float_as_uint(m));
        }
    }
}

// ---------------------------------------------------------------------------
// Partial sum of exp(x - M); 4 independent accumulator chains + 2-way load ILP.
__global__ __launch_bounds__(256) void k_sumexp(const float* __restrict__ out) {
    const int bk = blockIdx.y;
    const float4* p = (const float4*)(out + (size_t)bk * LL);
    const float M = __uint_as_float(g_maxbits[bk]);
    const float L2E = 1.4426950408889634f;
    const float nML2E = -M * L2E;
    const int STR = NPART * 256;
    float s0 = 0.f, s1 = 0.f, s2 = 0.f, s3 = 0.f;
    for (int t = blockIdx.x * 256 + threadIdx.x; t < LL4; t += 2 * STR) {
        float4 v = p[t];
        float4 u = make_float4(0.f, 0.f, 0.f, 0.f);
        int t2 = t + STR;
        bool hi = (t2 < LL4);
        if (hi) u = p[t2];
        s0 += exp2f(fmaf(v.x, L2E, nML2E));
        s1 += exp2f(fmaf(v.y, L2E, nML2E));
        s2 += exp2f(fmaf(v.z, L2E, nML2E));
        s3 += exp2f(fmaf(v.w, L2E, nML2E));
        if (hi) {
            s0 += exp2f(fmaf(u.x, L2E, nML2E));
            s1 += exp2f(fmaf(u.y, L2E, nML2E));
            s2 += exp2f(fmaf(u.z, L2E, nML2E));
            s3 += exp2f(fmaf(u.w, L2E, nML2E));
        }
    }
    float s = (s0 + s1) + (s2 + s3);
#pragma unroll
    for (int o = 16; o > 0; o >>= 1) s += __shfl_xor_sync(0xFFFFFFFFu, s, o);
    __shared__ float sm[8];
    if ((threadIdx.x & 31) == 0) sm[threadIdx.x >> 5] = s;
    __syncthreads();
    if (threadIdx.x == 0) {
        float ss = 0.f;
#pragma unroll
        for (int q = 0; q < 8; q++) ss += sm[q];
        g_psum[bk * NPART + blockIdx.x] = ss;  // fixed slot -> deterministic
    }
}

// Combine partials (fixed order) + subtract lse.
__global__ __launch_bounds__(256) void k_sub(float* __restrict__ out) {
    const int bk = blockIdx.y;
    __shared__ float lse_s;
    if (threadIdx.x == 0) {
        float M = __uint_as_float(g_maxbits[bk]);
        float s = 0.f;
#pragma unroll
        for (int q = 0; q < NPART; q++) s += g_psum[bk * NPART + q];
        lse_s = M + logf(s);
    }
    __syncthreads();
    const float lse = lse_s;
    int t = blockIdx.x * 256 + threadIdx.x;
    if (t < LL4) {
        float4* p = (float4*)(out + (size_t)bk * LL);
        float4 v = p[t];
        v.x -= lse;
        v.y -= lse;
        v.z -= lse;
        v.w -= lse;
        p[t] = v;
    }
}

// ---------------------------------------------------------------------------
extern "C" void kernel_launch(void* const* d_in, const int* in_sizes, int n_in,
                              void* d_out, int out_size) {
    const float* hidden = (const float*)d_in[0];
    const int* spans = (const int*)d_in[1];
    const int* smask = (const int*)d_in[2];
    const float* W1 = (const float*)d_in[3];
    const float* b1 = (const float*)d_in[4];
    const float* W2 = (const float*)d_in[5];
    const float* b2 = (const float*)d_in[6];
    float* out = (float*)d_out;

    cudaFuncSetAttribute(k_main, cudaFuncAttributeMaxDynamicSharedMemorySize, SMEM_MAIN);

    k_prep<<<256, 256>>>(W1, b1, W2);
    k_ph1<<<dim3(25, 8), 128>>>(hidden);
    k_zero<<<(BATCH * NLAB * LL4 + 511) / 512, 512>>>((float4*)out);
    k_main<<<dim3(4, 18, 2), 512, SMEM_MAIN>>>(spans, smask, b2, out);
    k_sumexp<<<dim3(NPART, BATCH * NLAB), 256>>>(out);
    k_sub<<<dim3((LL4 + 255) / 256, BATCH * NLAB), 256>>>(out);
}